// round 1
// baseline (speedup 1.0000x reference)
#include <cuda_runtime.h>
#include <math.h>

#define Bq   256
#define LOC  100
#define NSS  50
#define NN   150      /* LOC + NS */
#define BBD  64
#define FD   512
#define ED   576      /* FD + BBD */

/* ---------------- scratch (static device globals; no allocation) -------- */
__device__ float g_Wbb[BBD * 4];
__device__ float g_Wi [FD * 2048];
__device__ float g_Ws [FD * 300];
__device__ float g_Wl [ED * 2048];
__device__ float g_Wir[2048 * FD];
__device__ float g_Wsr[300 * FD];
__device__ float g_edges[(size_t)Bq * NN * ED];   /* [B,150,576]: fea0 | bb */
__device__ float g_lfa [Bq * ED];                 /* [B,576] */
__device__ float g_att [(size_t)Bq * NN * NN];    /* [B,150,150] */
__device__ float g_fea [(size_t)Bq * NN * FD];    /* [B,150,512] fea after attn */

/* ---------------- small helpers ---------------------------------------- */
__device__ __forceinline__ float warpSum(float v) {
#pragma unroll
    for (int o = 16; o; o >>= 1) v += __shfl_xor_sync(0xffffffffu, v, o);
    return v;
}
__device__ __forceinline__ float warpMax(float v) {
#pragma unroll
    for (int o = 16; o; o >>= 1) v = fmaxf(v, __shfl_xor_sync(0xffffffffu, v, o));
    return v;
}
__device__ float blockSum(float v, float* sh) {
    int lane = threadIdx.x & 31, w = threadIdx.x >> 5;
    v = warpSum(v);
    if (lane == 0) sh[w] = v;
    __syncthreads();
    if (threadIdx.x < 32) {
        int nw = blockDim.x >> 5;
        float x = (threadIdx.x < (unsigned)nw) ? sh[threadIdx.x] : 0.f;
        x = warpSum(x);
        if (threadIdx.x == 0) sh[0] = x;
    }
    __syncthreads();
    float r = sh[0];
    __syncthreads();
    return r;
}
__device__ float blockMax(float v, float* sh) {
    int lane = threadIdx.x & 31, w = threadIdx.x >> 5;
    v = warpMax(v);
    if (lane == 0) sh[w] = v;
    __syncthreads();
    if (threadIdx.x < 32) {
        int nw = blockDim.x >> 5;
        float x = (threadIdx.x < (unsigned)nw) ? sh[threadIdx.x] : -1e30f;
        x = warpMax(x);
        if (threadIdx.x == 0) sh[0] = x;
    }
    __syncthreads();
    float r = sh[0];
    __syncthreads();
    return r;
}

/* row remapping: GNN node layout [B,150,*]: rows of the i-part / s-part */
__device__ __forceinline__ int maprow(int m, int mode) {
    if (mode == 1) return (m / LOC) * NN + (m % LOC);
    if (mode == 2) return (m / NSS) * NN + LOC + (m % NSS);
    return m;
}

/* ---------------- weight normalization: W = v * g / ||v||_row ---------- */
__global__ void wnorm(const float* __restrict__ v, const float* __restrict__ g,
                      float* __restrict__ w, int K) {
    __shared__ float sh[32];
    int r = blockIdx.x;
    const float* vr = v + (size_t)r * K;
    float s = 0.f;
    for (int k = threadIdx.x; k < K; k += blockDim.x) { float x = vr[k]; s += x * x; }
    s = blockSum(s, sh);
    float scale = g[r] * rsqrtf(s);
    float* wr = w + (size_t)r * K;
    for (int k = threadIdx.x; k < K; k += blockDim.x) wr[k] = vr[k] * scale;
}

/* ---------------- bb = relu(cat(pi,ps) @ Wbb^T + b) into edges[:,512:] -- */
__global__ void bb_fill(const float* __restrict__ pi, const float* __restrict__ ps,
                        const float* __restrict__ Wbb, const float* __restrict__ bbb,
                        float* __restrict__ edges) {
    int idx = blockIdx.x * 256 + threadIdx.x;
    if (idx >= Bq * NN * BBD) return;
    int o  = idx % BBD;
    int rb = idx / BBD;
    int r = rb % NN, b = rb / NN;
    const float* p = (r < LOC) ? (pi + ((size_t)b * LOC + r) * 4)
                               : (ps + ((size_t)b * NSS + (r - LOC)) * 4);
    float acc = bbb[o];
#pragma unroll
    for (int k = 0; k < 4; k++) acc += p[k] * Wbb[o * 4 + k];
    edges[((size_t)b * NN + r) * ED + FD + o] = fmaxf(acc, 0.f);
}

/* ---------------- generic NT GEMM: C = relu(A @ W^T + bias) ------------ */
/* A [M,K] (rows remapped via amode), W [N,K], C row remapped via cmode    */
template <int BM, int BN, int BK, int TM, int TN>
__global__ void __launch_bounds__((BM / TM) * (BN / TN))
gemm_nt(const float* __restrict__ A, int lda, int amode,
        const float* __restrict__ W,
        const float* __restrict__ bias,
        float* __restrict__ C, int ldc, int cmode,
        int M, int N, int K) {
    constexpr int THREADS = (BM / TM) * (BN / TN);
    __shared__ float As[BK][BM];
    __shared__ float Bs[BK][BN];
    const int tid = threadIdx.x;
    const int m0 = blockIdx.y * BM, n0 = blockIdx.x * BN;
    const int tRow = (tid / (BN / TN)) * TM;
    const int tCol = (tid % (BN / TN)) * TN;
    const int K4 = K >> 2;

    float acc[TM][TN];
#pragma unroll
    for (int i = 0; i < TM; i++)
#pragma unroll
        for (int j = 0; j < TN; j++) acc[i][j] = 0.f;

    for (int k0 = 0; k0 < K; k0 += BK) {
        const int k04 = k0 >> 2;
#pragma unroll
        for (int i = tid; i < BM * (BK / 4); i += THREADS) {
            int row = i / (BK / 4);
            int kc4 = i % (BK / 4);
            float4 v = make_float4(0.f, 0.f, 0.f, 0.f);
            int gm = m0 + row, gk4 = k04 + kc4;
            if (gm < M && gk4 < K4) {
                long ar = maprow(gm, amode);
                v = *(const float4*)(A + ar * (long)lda + ((long)gk4 << 2));
            }
            int kk = kc4 * 4;
            As[kk + 0][row] = v.x; As[kk + 1][row] = v.y;
            As[kk + 2][row] = v.z; As[kk + 3][row] = v.w;
        }
#pragma unroll
        for (int i = tid; i < BN * (BK / 4); i += THREADS) {
            int row = i / (BK / 4);
            int kc4 = i % (BK / 4);
            float4 v = make_float4(0.f, 0.f, 0.f, 0.f);
            int gn = n0 + row, gk4 = k04 + kc4;
            if (gn < N && gk4 < K4)
                v = *(const float4*)(W + (long)gn * K + ((long)gk4 << 2));
            int kk = kc4 * 4;
            Bs[kk + 0][row] = v.x; Bs[kk + 1][row] = v.y;
            Bs[kk + 2][row] = v.z; Bs[kk + 3][row] = v.w;
        }
        __syncthreads();
#pragma unroll
        for (int k = 0; k < BK; k++) {
            float ra[TM], rb[TN];
#pragma unroll
            for (int i = 0; i < TM; i++) ra[i] = As[k][tRow + i];
#pragma unroll
            for (int j = 0; j < TN; j++) rb[j] = Bs[k][tCol + j];
#pragma unroll
            for (int i = 0; i < TM; i++)
#pragma unroll
                for (int j = 0; j < TN; j++) acc[i][j] += ra[i] * rb[j];
        }
        __syncthreads();
    }

#pragma unroll
    for (int i = 0; i < TM; i++) {
        int gm = m0 + tRow + i;
        if (gm >= M) continue;
        long cr = maprow(gm, cmode);
#pragma unroll
        for (int j = 0; j < TN; j++) {
            int gn = n0 + tCol + j;
            if (gn < N)
                C[cr * (long)ldc + gn] = fmaxf(acc[i][j] + bias[gn], 0.f);
        }
    }
}

/* ---------------- softmax over 576-dim rows of l_fa (after relu) ------- */
__global__ void lsoftmax(float* __restrict__ lfa) {
    __shared__ float sh[32];
    float* a = lfa + (size_t)blockIdx.x * ED;
    float mx = -1e30f;
    for (int j = threadIdx.x; j < ED; j += blockDim.x) mx = fmaxf(mx, a[j]);
    mx = blockMax(mx, sh);
    float s = 0.f;
    for (int j = threadIdx.x; j < ED; j += blockDim.x) {
        float e = expf(a[j] - mx);
        a[j] = e; s += e;
    }
    s = blockSum(s, sh);
    float inv = 1.f / s;
    for (int j = threadIdx.x; j < ED; j += blockDim.x) a[j] *= inv;
}

/* ---------------- att scores: S[r,c] = sum_d E[r,d]*lf[d]*E[c,d] ------- */
/* per batch; 64x64 output tile, 4x4 microtile, d-chunks of 16            */
__global__ void __launch_bounds__(256)
att_score(const float* __restrict__ edges, const float* __restrict__ lfa,
          float* __restrict__ att) {
    int b = blockIdx.z;
    int r0 = blockIdx.y * 64, c0 = blockIdx.x * 64;
    __shared__ float Ea[16][64], Eb[16][64];
    const float* E  = edges + (size_t)b * NN * ED;
    const float* lf = lfa + (size_t)b * ED;
    int tid = threadIdx.x;
    int ty = tid / 16, tx = tid % 16;
    int rr = tid / 4,  d4 = tid % 4;
    float acc[4][4];
#pragma unroll
    for (int i = 0; i < 4; i++)
#pragma unroll
        for (int j = 0; j < 4; j++) acc[i][j] = 0.f;

    for (int d0 = 0; d0 < ED; d0 += 16) {
        float4 lf4 = *(const float4*)(lf + d0 + d4 * 4);
        float4 va = make_float4(0.f, 0.f, 0.f, 0.f), vb = va;
        if (r0 + rr < NN) {
            va = *(const float4*)(E + (size_t)(r0 + rr) * ED + d0 + d4 * 4);
            va.x *= lf4.x; va.y *= lf4.y; va.z *= lf4.z; va.w *= lf4.w;
        }
        if (c0 + rr < NN)
            vb = *(const float4*)(E + (size_t)(c0 + rr) * ED + d0 + d4 * 4);
        int kk = d4 * 4;
        Ea[kk + 0][rr] = va.x; Ea[kk + 1][rr] = va.y;
        Ea[kk + 2][rr] = va.z; Ea[kk + 3][rr] = va.w;
        Eb[kk + 0][rr] = vb.x; Eb[kk + 1][rr] = vb.y;
        Eb[kk + 2][rr] = vb.z; Eb[kk + 3][rr] = vb.w;
        __syncthreads();
#pragma unroll
        for (int d = 0; d < 16; d++) {
            float ra[4], rb[4];
#pragma unroll
            for (int i = 0; i < 4; i++) ra[i] = Ea[d][ty * 4 + i];
#pragma unroll
            for (int j = 0; j < 4; j++) rb[j] = Eb[d][tx * 4 + j];
#pragma unroll
            for (int i = 0; i < 4; i++)
#pragma unroll
                for (int j = 0; j < 4; j++) acc[i][j] += ra[i] * rb[j];
        }
        __syncthreads();
    }
#pragma unroll
    for (int i = 0; i < 4; i++) {
        int r = r0 + ty * 4 + i;
        if (r >= NN) continue;
#pragma unroll
        for (int j = 0; j < 4; j++) {
            int c = c0 + tx * 4 + j;
            if (c < NN) att[((size_t)b * NN + r) * NN + c] = acc[i][j];
        }
    }
}

/* ---------------- mask + row softmax over 150 cols --------------------- */
/* allowed(r,c): r>=ms -> all c; r<ms -> c<ms. one block per (b,r)        */
__global__ void att_mask_softmax(float* __restrict__ att, const int* __restrict__ mask_s) {
    __shared__ float sh[32];
    int row = blockIdx.x;
    int b = row / NN, r = row % NN;
    int ms = mask_s[b];
    int limit = (r >= ms) ? NN : ms;
    float* a = att + (size_t)row * NN;
    int t = threadIdx.x;
    float v = (t < limit) ? a[t] : -1e30f;
    float mx = blockMax(v, sh);
    float e = (t < limit) ? expf(v - mx) : 0.f;
    float s = blockSum(e, sh);
    if (t < NN) a[t] = e / s;
}

/* ---------------- fea = fea0 + tanh(att @ fea0) ------------------------ */
/* block = (batch, 16-row chunk); att rows cached in smem                  */
__global__ void __launch_bounds__(256)
att_apply(const float* __restrict__ att, const float* __restrict__ edges,
          float* __restrict__ fea) {
    __shared__ float sa[16][NN];
    int b = blockIdx.x, m0 = blockIdx.y * 16;
    const float* ab = att + (size_t)b * NN * NN;
    for (int i = threadIdx.x; i < 16 * NN; i += 256) {
        int mm = i / NN, k = i % NN;
        sa[mm][k] = (m0 + mm < NN) ? ab[(size_t)(m0 + mm) * NN + k] : 0.f;
    }
    __syncthreads();
    const float* E = edges + (size_t)b * NN * ED;
    for (int nrep = 0; nrep < 2; nrep++) {
        int n = threadIdx.x + nrep * 256;
        float acc[16];
#pragma unroll
        for (int mm = 0; mm < 16; mm++) acc[mm] = 0.f;
#pragma unroll 2
        for (int k = 0; k < NN; k++) {
            float e = E[(size_t)k * ED + n];
#pragma unroll
            for (int mm = 0; mm < 16; mm++) acc[mm] += sa[mm][k] * e;
        }
#pragma unroll
        for (int mm = 0; mm < 16; mm++) {
            int m = m0 + mm;
            if (m < NN)
                fea[((size_t)b * NN + m) * FD + n] =
                    E[(size_t)m * ED + n] + tanhf(acc[mm]);
        }
    }
}

/* ---------------- launch --------------------------------------------- */
extern "C" void kernel_launch(void* const* d_in, const int* in_sizes, int n_in,
                              void* d_out, int out_size) {
    const float* l   = (const float*)d_in[0];
    const float* iin = (const float*)d_in[1];
    const float* sin = (const float*)d_in[2];
    const float* pi  = (const float*)d_in[3];
    const float* ps  = (const float*)d_in[4];
    const int*   ms  = (const int*)  d_in[5];
    /* 18 weight arrays at the tail (bb/i/s/l/ir/sr × v,g,b); anchor on n_in
       so the scalar `it` slot is tolerated whether or not it materializes. */
    int w0 = n_in - 18;
    const float* bb_v = (const float*)d_in[w0 + 0];
    const float* bb_g = (const float*)d_in[w0 + 1];
    const float* bb_b = (const float*)d_in[w0 + 2];
    const float* i_v  = (const float*)d_in[w0 + 3];
    const float* i_g  = (const float*)d_in[w0 + 4];
    const float* i_b  = (const float*)d_in[w0 + 5];
    const float* s_v  = (const float*)d_in[w0 + 6];
    const float* s_g  = (const float*)d_in[w0 + 7];
    const float* s_b  = (const float*)d_in[w0 + 8];
    const float* l_v  = (const float*)d_in[w0 + 9];
    const float* l_g  = (const float*)d_in[w0 + 10];
    const float* l_b  = (const float*)d_in[w0 + 11];
    const float* ir_v = (const float*)d_in[w0 + 12];
    const float* ir_g = (const float*)d_in[w0 + 13];
    const float* ir_b = (const float*)d_in[w0 + 14];
    const float* sr_v = (const float*)d_in[w0 + 15];
    const float* sr_g = (const float*)d_in[w0 + 16];
    const float* sr_b = (const float*)d_in[w0 + 17];
    float* out = (float*)d_out;
    (void)in_sizes; (void)out_size;

    float *Wbb, *Wi, *Ws, *Wl, *Wir, *Wsr, *edges, *lfa, *att, *fea;
    cudaGetSymbolAddress((void**)&Wbb, g_Wbb);
    cudaGetSymbolAddress((void**)&Wi,  g_Wi);
    cudaGetSymbolAddress((void**)&Ws,  g_Ws);
    cudaGetSymbolAddress((void**)&Wl,  g_Wl);
    cudaGetSymbolAddress((void**)&Wir, g_Wir);
    cudaGetSymbolAddress((void**)&Wsr, g_Wsr);
    cudaGetSymbolAddress((void**)&edges, g_edges);
    cudaGetSymbolAddress((void**)&lfa, g_lfa);
    cudaGetSymbolAddress((void**)&att, g_att);
    cudaGetSymbolAddress((void**)&fea, g_fea);

    /* weight-norm all matrices */
    wnorm<<<BBD,  256>>>(bb_v, bb_g, Wbb, 4);
    wnorm<<<FD,   256>>>(i_v,  i_g,  Wi,  2048);
    wnorm<<<FD,   256>>>(s_v,  s_g,  Ws,  300);
    wnorm<<<ED,   256>>>(l_v,  l_g,  Wl,  2048);
    wnorm<<<2048, 256>>>(ir_v, ir_g, Wir, FD);
    wnorm<<<300,  256>>>(sr_v, sr_g, Wsr, FD);

    /* bb features into edges[:, :, 512:576] */
    bb_fill<<<(Bq * NN * BBD + 255) / 256, 256>>>(pi, ps, Wbb, bb_b, edges);

    /* i_fa, s_fa into edges[:, :, 0:512] */
    gemm_nt<128, 128, 16, 8, 8><<<dim3(FD / 128, (Bq * LOC) / 128), 256>>>(
        iin, 2048, 0, Wi, i_b, edges, ED, 1, Bq * LOC, FD, 2048);
    gemm_nt<128, 128, 16, 8, 8><<<dim3(FD / 128, (Bq * NSS) / 128), 256>>>(
        sin, 300, 0, Ws, s_b, edges, ED, 2, Bq * NSS, FD, 300);

    /* l_fa = softmax(relu(l @ Wl^T)) */
    gemm_nt<64, 64, 16, 4, 4><<<dim3((ED + 63) / 64, (Bq + 63) / 64), 256>>>(
        l, 2048, 0, Wl, l_b, lfa, ED, 0, Bq, ED, 2048);
    lsoftmax<<<Bq, 256>>>(lfa);

    /* attention */
    att_score<<<dim3(3, 3, Bq), 256>>>(edges, lfa, att);
    att_mask_softmax<<<Bq * NN, 256>>>(att, ms);
    att_apply<<<dim3(Bq, 10), 256>>>(att, edges, fea);

    /* output heads */
    gemm_nt<128, 128, 16, 8, 8><<<dim3(2048 / 128, (Bq * LOC) / 128), 256>>>(
        fea, FD, 1, Wir, ir_b, out, 2048, 0, Bq * LOC, 2048, FD);
    gemm_nt<128, 128, 16, 8, 8><<<dim3((300 + 127) / 128, (Bq * NSS) / 128), 256>>>(
        fea, FD, 2, Wsr, sr_b, out + (size_t)Bq * LOC * 2048, 300, 0,
        Bq * NSS, 300, FD);
}

// round 2
// speedup vs baseline: 2.1881x; 2.1881x over previous
#include <cuda_runtime.h>
#include <math.h>
#include <stdint.h>

#define Bq   256
#define LOC  100
#define NSS  50
#define NN   150      /* LOC + NS */
#define BBD  64
#define FD   512
#define ED   576      /* FD + BBD */

/* ---------------- scratch (static device globals; no allocation) -------- */
__device__ float g_Wbb[BBD * 4];
__device__ float g_Wi [FD * 2048];
__device__ float g_Ws [FD * 300];
__device__ float g_Wl [ED * 2048];
__device__ float g_Wir[2048 * FD];
__device__ float g_Wsr[300 * FD];
__device__ float g_edges[(size_t)Bq * NN * ED];   /* [B,150,576]: fea0 | bb */
__device__ float g_lfa [Bq * ED];                 /* [B,576] */
__device__ float g_att [(size_t)Bq * NN * NN];    /* [B,150,150] */
__device__ float g_fea [(size_t)Bq * NN * FD];    /* [B,150,512] fea after attn */

/* ---------------- small helpers ---------------------------------------- */
__device__ __forceinline__ float warpSum(float v) {
#pragma unroll
    for (int o = 16; o; o >>= 1) v += __shfl_xor_sync(0xffffffffu, v, o);
    return v;
}
__device__ __forceinline__ float warpMax(float v) {
#pragma unroll
    for (int o = 16; o; o >>= 1) v = fmaxf(v, __shfl_xor_sync(0xffffffffu, v, o));
    return v;
}
__device__ float blockSum(float v, float* sh) {
    int lane = threadIdx.x & 31, w = threadIdx.x >> 5;
    v = warpSum(v);
    if (lane == 0) sh[w] = v;
    __syncthreads();
    if (threadIdx.x < 32) {
        int nw = blockDim.x >> 5;
        float x = (threadIdx.x < (unsigned)nw) ? sh[threadIdx.x] : 0.f;
        x = warpSum(x);
        if (threadIdx.x == 0) sh[0] = x;
    }
    __syncthreads();
    float r = sh[0];
    __syncthreads();
    return r;
}
__device__ float blockMax(float v, float* sh) {
    int lane = threadIdx.x & 31, w = threadIdx.x >> 5;
    v = warpMax(v);
    if (lane == 0) sh[w] = v;
    __syncthreads();
    if (threadIdx.x < 32) {
        int nw = blockDim.x >> 5;
        float x = (threadIdx.x < (unsigned)nw) ? sh[threadIdx.x] : -1e30f;
        x = warpMax(x);
        if (threadIdx.x == 0) sh[0] = x;
    }
    __syncthreads();
    float r = sh[0];
    __syncthreads();
    return r;
}

/* row remapping: GNN node layout [B,150,*]: rows of the i-part / s-part */
__device__ __forceinline__ int maprow(int m, int mode) {
    if (mode == 1) return (m / LOC) * NN + (m % LOC);
    if (mode == 2) return (m / NSS) * NN + LOC + (m % NSS);
    return m;
}

__device__ __forceinline__ uint32_t f2tf32(float f) {
    uint32_t r;
    asm("cvt.rna.tf32.f32 %0, %1;" : "=r"(r) : "f"(f));
    return r;
}

__device__ __forceinline__ void mma_tf32(float (&d)[4], const uint32_t (&a)[4],
                                         const uint32_t (&b)[2]) {
    asm volatile(
        "mma.sync.aligned.m16n8k8.row.col.f32.tf32.tf32.f32 "
        "{%0,%1,%2,%3}, {%4,%5,%6,%7}, {%8,%9}, {%0,%1,%2,%3};\n"
        : "+f"(d[0]), "+f"(d[1]), "+f"(d[2]), "+f"(d[3])
        : "r"(a[0]), "r"(a[1]), "r"(a[2]), "r"(a[3]), "r"(b[0]), "r"(b[1]));
}

/* ---------------- weight normalization: W = v * g / ||v||_row ---------- */
__global__ void wnorm(const float* __restrict__ v, const float* __restrict__ g,
                      float* __restrict__ w, int K) {
    __shared__ float sh[32];
    int r = blockIdx.x;
    const float* vr = v + (size_t)r * K;
    float s = 0.f;
    for (int k = threadIdx.x; k < K; k += blockDim.x) { float x = vr[k]; s += x * x; }
    s = blockSum(s, sh);
    float scale = g[r] * rsqrtf(s);
    float* wr = w + (size_t)r * K;
    for (int k = threadIdx.x; k < K; k += blockDim.x) wr[k] = vr[k] * scale;
}

/* ---------------- bb = relu(cat(pi,ps) @ Wbb^T + b) into edges[:,512:] -- */
__global__ void bb_fill(const float* __restrict__ pi, const float* __restrict__ ps,
                        const float* __restrict__ Wbb, const float* __restrict__ bbb,
                        float* __restrict__ edges) {
    int idx = blockIdx.x * 256 + threadIdx.x;
    if (idx >= Bq * NN * BBD) return;
    int o  = idx % BBD;
    int rb = idx / BBD;
    int r = rb % NN, b = rb / NN;
    const float* p = (r < LOC) ? (pi + ((size_t)b * LOC + r) * 4)
                               : (ps + ((size_t)b * NSS + (r - LOC)) * 4);
    float acc = bbb[o];
#pragma unroll
    for (int k = 0; k < 4; k++) acc += p[k] * Wbb[o * 4 + k];
    edges[((size_t)b * NN + r) * ED + FD + o] = fmaxf(acc, 0.f);
}

/* ---------------- TF32 tensor-core NT GEMM: C = relu(A @ W^T + bias) ---- */
/* Block 128x128, BK=32, 8 warps, warp tile 64x32, mma m16n8k8 tf32.       */
__global__ void __launch_bounds__(256)
gemm_tf32(const float* __restrict__ A, int lda, int amode,
          const float* __restrict__ W,
          const float* __restrict__ bias,
          float* __restrict__ C, int ldc, int cmode,
          int M, int N, int K) {
    __shared__ uint32_t As[128][36];
    __shared__ uint32_t Bs[128][36];
    const int tid = threadIdx.x;
    const int lane = tid & 31, wid = tid >> 5;
    const int wm = (wid & 1) * 64;      /* warp m offset in block tile */
    const int wn = (wid >> 1) * 32;     /* warp n offset */
    const int m0 = blockIdx.y * 128, n0 = blockIdx.x * 128;

    float acc[4][4][4];
#pragma unroll
    for (int mi = 0; mi < 4; mi++)
#pragma unroll
        for (int ni = 0; ni < 4; ni++)
#pragma unroll
            for (int q = 0; q < 4; q++) acc[mi][ni][q] = 0.f;

    for (int k0 = 0; k0 < K; k0 += 32) {
        /* load A tile: 128 rows x 32 cols, tf32-converted */
#pragma unroll
        for (int t = 0; t < 4; t++) {
            int i = tid + t * 256;          /* 1024 float4 slots */
            int row = i >> 3, kc4 = i & 7;
            int gm = m0 + row, gk = k0 + kc4 * 4;
            float4 v = make_float4(0.f, 0.f, 0.f, 0.f);
            if (gm < M && gk < K) {
                long ar = maprow(gm, amode);
                v = *(const float4*)(A + ar * (long)lda + gk);
            }
            As[row][kc4 * 4 + 0] = f2tf32(v.x);
            As[row][kc4 * 4 + 1] = f2tf32(v.y);
            As[row][kc4 * 4 + 2] = f2tf32(v.z);
            As[row][kc4 * 4 + 3] = f2tf32(v.w);
        }
        /* load B tile: W[N,K] rows n0..n0+127 */
#pragma unroll
        for (int t = 0; t < 4; t++) {
            int i = tid + t * 256;
            int row = i >> 3, kc4 = i & 7;
            int gn = n0 + row, gk = k0 + kc4 * 4;
            float4 v = make_float4(0.f, 0.f, 0.f, 0.f);
            if (gn < N && gk < K)
                v = *(const float4*)(W + (long)gn * K + gk);
            Bs[row][kc4 * 4 + 0] = f2tf32(v.x);
            Bs[row][kc4 * 4 + 1] = f2tf32(v.y);
            Bs[row][kc4 * 4 + 2] = f2tf32(v.z);
            Bs[row][kc4 * 4 + 3] = f2tf32(v.w);
        }
        __syncthreads();

#pragma unroll
        for (int ks = 0; ks < 4; ks++) {
            int kb = ks * 8;
            uint32_t afr[4][4], bfr[4][2];
            int ar0 = wm + (lane >> 2);
            int ac  = kb + (lane & 3);
#pragma unroll
            for (int mi = 0; mi < 4; mi++) {
                afr[mi][0] = As[ar0 + mi * 16    ][ac];
                afr[mi][1] = As[ar0 + mi * 16 + 8][ac];
                afr[mi][2] = As[ar0 + mi * 16    ][ac + 4];
                afr[mi][3] = As[ar0 + mi * 16 + 8][ac + 4];
            }
            int br0 = wn + (lane >> 2);
#pragma unroll
            for (int ni = 0; ni < 4; ni++) {
                bfr[ni][0] = Bs[br0 + ni * 8][kb + (lane & 3)];
                bfr[ni][1] = Bs[br0 + ni * 8][kb + (lane & 3) + 4];
            }
#pragma unroll
            for (int mi = 0; mi < 4; mi++)
#pragma unroll
                for (int ni = 0; ni < 4; ni++)
                    mma_tf32(acc[mi][ni], afr[mi], bfr[ni]);
        }
        __syncthreads();
    }

    /* epilogue: bias + relu, remapped rows */
#pragma unroll
    for (int mi = 0; mi < 4; mi++) {
#pragma unroll
        for (int half = 0; half < 2; half++) {
            int gm = m0 + wm + mi * 16 + (lane >> 2) + half * 8;
            if (gm >= M) continue;
            long cr = maprow(gm, cmode);
#pragma unroll
            for (int ni = 0; ni < 4; ni++) {
                int gn = n0 + wn + ni * 8 + (lane & 3) * 2;
                float c0 = acc[mi][ni][half * 2 + 0];
                float c1 = acc[mi][ni][half * 2 + 1];
                if (gn < N)
                    C[cr * (long)ldc + gn] = fmaxf(c0 + bias[gn], 0.f);
                if (gn + 1 < N)
                    C[cr * (long)ldc + gn + 1] = fmaxf(c1 + bias[gn + 1], 0.f);
            }
        }
    }
}

/* ---------------- fp32 NT GEMM (kept for the tiny l projection) --------- */
template <int BM, int BN, int BK, int TM, int TN>
__global__ void __launch_bounds__((BM / TM) * (BN / TN))
gemm_nt(const float* __restrict__ A, int lda, int amode,
        const float* __restrict__ W,
        const float* __restrict__ bias,
        float* __restrict__ C, int ldc, int cmode,
        int M, int N, int K) {
    constexpr int THREADS = (BM / TM) * (BN / TN);
    __shared__ float As[BK][BM];
    __shared__ float Bs[BK][BN];
    const int tid = threadIdx.x;
    const int m0 = blockIdx.y * BM, n0 = blockIdx.x * BN;
    const int tRow = (tid / (BN / TN)) * TM;
    const int tCol = (tid % (BN / TN)) * TN;
    const int K4 = K >> 2;

    float acc[TM][TN];
#pragma unroll
    for (int i = 0; i < TM; i++)
#pragma unroll
        for (int j = 0; j < TN; j++) acc[i][j] = 0.f;

    for (int k0 = 0; k0 < K; k0 += BK) {
        const int k04 = k0 >> 2;
#pragma unroll
        for (int i = tid; i < BM * (BK / 4); i += THREADS) {
            int row = i / (BK / 4);
            int kc4 = i % (BK / 4);
            float4 v = make_float4(0.f, 0.f, 0.f, 0.f);
            int gm = m0 + row, gk4 = k04 + kc4;
            if (gm < M && gk4 < K4) {
                long ar = maprow(gm, amode);
                v = *(const float4*)(A + ar * (long)lda + ((long)gk4 << 2));
            }
            int kk = kc4 * 4;
            As[kk + 0][row] = v.x; As[kk + 1][row] = v.y;
            As[kk + 2][row] = v.z; As[kk + 3][row] = v.w;
        }
#pragma unroll
        for (int i = tid; i < BN * (BK / 4); i += THREADS) {
            int row = i / (BK / 4);
            int kc4 = i % (BK / 4);
            float4 v = make_float4(0.f, 0.f, 0.f, 0.f);
            int gn = n0 + row, gk4 = k04 + kc4;
            if (gn < N && gk4 < K4)
                v = *(const float4*)(W + (long)gn * K + ((long)gk4 << 2));
            int kk = kc4 * 4;
            Bs[kk + 0][row] = v.x; Bs[kk + 1][row] = v.y;
            Bs[kk + 2][row] = v.z; Bs[kk + 3][row] = v.w;
        }
        __syncthreads();
#pragma unroll
        for (int k = 0; k < BK; k++) {
            float ra[TM], rb[TN];
#pragma unroll
            for (int i = 0; i < TM; i++) ra[i] = As[k][tRow + i];
#pragma unroll
            for (int j = 0; j < TN; j++) rb[j] = Bs[k][tCol + j];
#pragma unroll
            for (int i = 0; i < TM; i++)
#pragma unroll
                for (int j = 0; j < TN; j++) acc[i][j] += ra[i] * rb[j];
        }
        __syncthreads();
    }

#pragma unroll
    for (int i = 0; i < TM; i++) {
        int gm = m0 + tRow + i;
        if (gm >= M) continue;
        long cr = maprow(gm, cmode);
#pragma unroll
        for (int j = 0; j < TN; j++) {
            int gn = n0 + tCol + j;
            if (gn < N)
                C[cr * (long)ldc + gn] = fmaxf(acc[i][j] + bias[gn], 0.f);
        }
    }
}

/* ---------------- softmax over 576-dim rows of l_fa (after relu) ------- */
__global__ void lsoftmax(float* __restrict__ lfa) {
    __shared__ float sh[32];
    float* a = lfa + (size_t)blockIdx.x * ED;
    float mx = -1e30f;
    for (int j = threadIdx.x; j < ED; j += blockDim.x) mx = fmaxf(mx, a[j]);
    mx = blockMax(mx, sh);
    float s = 0.f;
    for (int j = threadIdx.x; j < ED; j += blockDim.x) {
        float e = expf(a[j] - mx);
        a[j] = e; s += e;
    }
    s = blockSum(s, sh);
    float inv = 1.f / s;
    for (int j = threadIdx.x; j < ED; j += blockDim.x) a[j] *= inv;
}

/* ---------------- att scores: S[r,c] = sum_d E[r,d]*lf[d]*E[c,d] ------- */
__global__ void __launch_bounds__(256)
att_score(const float* __restrict__ edges, const float* __restrict__ lfa,
          float* __restrict__ att) {
    int b = blockIdx.z;
    int r0 = blockIdx.y * 64, c0 = blockIdx.x * 64;
    __shared__ float Ea[16][64], Eb[16][64];
    const float* E  = edges + (size_t)b * NN * ED;
    const float* lf = lfa + (size_t)b * ED;
    int tid = threadIdx.x;
    int ty = tid / 16, tx = tid % 16;
    int rr = tid / 4,  d4 = tid % 4;
    float acc[4][4];
#pragma unroll
    for (int i = 0; i < 4; i++)
#pragma unroll
        for (int j = 0; j < 4; j++) acc[i][j] = 0.f;

    for (int d0 = 0; d0 < ED; d0 += 16) {
        float4 lf4 = *(const float4*)(lf + d0 + d4 * 4);
        float4 va = make_float4(0.f, 0.f, 0.f, 0.f), vb = va;
        if (r0 + rr < NN) {
            va = *(const float4*)(E + (size_t)(r0 + rr) * ED + d0 + d4 * 4);
            va.x *= lf4.x; va.y *= lf4.y; va.z *= lf4.z; va.w *= lf4.w;
        }
        if (c0 + rr < NN)
            vb = *(const float4*)(E + (size_t)(c0 + rr) * ED + d0 + d4 * 4);
        int kk = d4 * 4;
        Ea[kk + 0][rr] = va.x; Ea[kk + 1][rr] = va.y;
        Ea[kk + 2][rr] = va.z; Ea[kk + 3][rr] = va.w;
        Eb[kk + 0][rr] = vb.x; Eb[kk + 1][rr] = vb.y;
        Eb[kk + 2][rr] = vb.z; Eb[kk + 3][rr] = vb.w;
        __syncthreads();
#pragma unroll
        for (int d = 0; d < 16; d++) {
            float ra[4], rb[4];
#pragma unroll
            for (int i = 0; i < 4; i++) ra[i] = Ea[d][ty * 4 + i];
#pragma unroll
            for (int j = 0; j < 4; j++) rb[j] = Eb[d][tx * 4 + j];
#pragma unroll
            for (int i = 0; i < 4; i++)
#pragma unroll
                for (int j = 0; j < 4; j++) acc[i][j] += ra[i] * rb[j];
        }
        __syncthreads();
    }
#pragma unroll
    for (int i = 0; i < 4; i++) {
        int r = r0 + ty * 4 + i;
        if (r >= NN) continue;
#pragma unroll
        for (int j = 0; j < 4; j++) {
            int c = c0 + tx * 4 + j;
            if (c < NN) att[((size_t)b * NN + r) * NN + c] = acc[i][j];
        }
    }
}

/* ---------------- mask + row softmax over 150 cols --------------------- */
__global__ void att_mask_softmax(float* __restrict__ att, const int* __restrict__ mask_s) {
    __shared__ float sh[32];
    int row = blockIdx.x;
    int b = row / NN, r = row % NN;
    int ms = mask_s[b];
    int limit = (r >= ms) ? NN : ms;
    float* a = att + (size_t)row * NN;
    int t = threadIdx.x;
    float v = (t < limit) ? a[t] : -1e30f;
    float mx = blockMax(v, sh);
    float e = (t < limit) ? expf(v - mx) : 0.f;
    float s = blockSum(e, sh);
    if (t < NN) a[t] = e / s;
}

/* ---------------- fea = fea0 + tanh(att @ fea0) ------------------------ */
__global__ void __launch_bounds__(256)
att_apply(const float* __restrict__ att, const float* __restrict__ edges,
          float* __restrict__ fea) {
    __shared__ float sa[16][NN];
    int b = blockIdx.x, m0 = blockIdx.y * 16;
    const float* ab = att + (size_t)b * NN * NN;
    for (int i = threadIdx.x; i < 16 * NN; i += 256) {
        int mm = i / NN, k = i % NN;
        sa[mm][k] = (m0 + mm < NN) ? ab[(size_t)(m0 + mm) * NN + k] : 0.f;
    }
    __syncthreads();
    const float* E = edges + (size_t)b * NN * ED;
    for (int nrep = 0; nrep < 2; nrep++) {
        int n = threadIdx.x + nrep * 256;
        float acc[16];
#pragma unroll
        for (int mm = 0; mm < 16; mm++) acc[mm] = 0.f;
#pragma unroll 2
        for (int k = 0; k < NN; k++) {
            float e = E[(size_t)k * ED + n];
#pragma unroll
            for (int mm = 0; mm < 16; mm++) acc[mm] += sa[mm][k] * e;
        }
#pragma unroll
        for (int mm = 0; mm < 16; mm++) {
            int m = m0 + mm;
            if (m < NN)
                fea[((size_t)b * NN + m) * FD + n] =
                    E[(size_t)m * ED + n] + tanhf(acc[mm]);
        }
    }
}

/* ---------------- launch --------------------------------------------- */
extern "C" void kernel_launch(void* const* d_in, const int* in_sizes, int n_in,
                              void* d_out, int out_size) {
    const float* l   = (const float*)d_in[0];
    const float* iin = (const float*)d_in[1];
    const float* sin = (const float*)d_in[2];
    const float* pi  = (const float*)d_in[3];
    const float* ps  = (const float*)d_in[4];
    const int*   ms  = (const int*)  d_in[5];
    int w0 = n_in - 18;
    const float* bb_v = (const float*)d_in[w0 + 0];
    const float* bb_g = (const float*)d_in[w0 + 1];
    const float* bb_b = (const float*)d_in[w0 + 2];
    const float* i_v  = (const float*)d_in[w0 + 3];
    const float* i_g  = (const float*)d_in[w0 + 4];
    const float* i_b  = (const float*)d_in[w0 + 5];
    const float* s_v  = (const float*)d_in[w0 + 6];
    const float* s_g  = (const float*)d_in[w0 + 7];
    const float* s_b  = (const float*)d_in[w0 + 8];
    const float* l_v  = (const float*)d_in[w0 + 9];
    const float* l_g  = (const float*)d_in[w0 + 10];
    const float* l_b  = (const float*)d_in[w0 + 11];
    const float* ir_v = (const float*)d_in[w0 + 12];
    const float* ir_g = (const float*)d_in[w0 + 13];
    const float* ir_b = (const float*)d_in[w0 + 14];
    const float* sr_v = (const float*)d_in[w0 + 15];
    const float* sr_g = (const float*)d_in[w0 + 16];
    const float* sr_b = (const float*)d_in[w0 + 17];
    float* out = (float*)d_out;
    (void)in_sizes; (void)out_size;

    float *Wbb, *Wi, *Ws, *Wl, *Wir, *Wsr, *edges, *lfa, *att, *fea;
    cudaGetSymbolAddress((void**)&Wbb, g_Wbb);
    cudaGetSymbolAddress((void**)&Wi,  g_Wi);
    cudaGetSymbolAddress((void**)&Ws,  g_Ws);
    cudaGetSymbolAddress((void**)&Wl,  g_Wl);
    cudaGetSymbolAddress((void**)&Wir, g_Wir);
    cudaGetSymbolAddress((void**)&Wsr, g_Wsr);
    cudaGetSymbolAddress((void**)&edges, g_edges);
    cudaGetSymbolAddress((void**)&lfa, g_lfa);
    cudaGetSymbolAddress((void**)&att, g_att);
    cudaGetSymbolAddress((void**)&fea, g_fea);

    /* weight-norm all matrices */
    wnorm<<<BBD,  256>>>(bb_v, bb_g, Wbb, 4);
    wnorm<<<FD,   256>>>(i_v,  i_g,  Wi,  2048);
    wnorm<<<FD,   256>>>(s_v,  s_g,  Ws,  300);
    wnorm<<<ED,   256>>>(l_v,  l_g,  Wl,  2048);
    wnorm<<<2048, 256>>>(ir_v, ir_g, Wir, FD);
    wnorm<<<300,  256>>>(sr_v, sr_g, Wsr, FD);

    /* bb features into edges[:, :, 512:576] */
    bb_fill<<<(Bq * NN * BBD + 255) / 256, 256>>>(pi, ps, Wbb, bb_b, edges);

    /* i_fa, s_fa into edges[:, :, 0:512]  (tf32 tensor cores) */
    gemm_tf32<<<dim3(FD / 128, (Bq * LOC) / 128), 256>>>(
        iin, 2048, 0, Wi, i_b, edges, ED, 1, Bq * LOC, FD, 2048);
    gemm_tf32<<<dim3(FD / 128, (Bq * NSS) / 128), 256>>>(
        sin, 300, 0, Ws, s_b, edges, ED, 2, Bq * NSS, FD, 300);

    /* l_fa = softmax(relu(l @ Wl^T))  (small, fp32) */
    gemm_nt<64, 64, 16, 4, 4><<<dim3((ED + 63) / 64, (Bq + 63) / 64), 256>>>(
        l, 2048, 0, Wl, l_b, lfa, ED, 0, Bq, ED, 2048);
    lsoftmax<<<Bq, 256>>>(lfa);

    /* attention */
    att_score<<<dim3(3, 3, Bq), 256>>>(edges, lfa, att);
    att_mask_softmax<<<Bq * NN, 256>>>(att, ms);
    att_apply<<<dim3(Bq, 10), 256>>>(att, edges, fea);

    /* output heads (tf32 tensor cores) */
    gemm_tf32<<<dim3(2048 / 128, (Bq * LOC) / 128), 256>>>(
        fea, FD, 1, Wir, ir_b, out, 2048, 0, Bq * LOC, 2048, FD);
    gemm_tf32<<<dim3((300 + 127) / 128, (Bq * NSS) / 128), 256>>>(
        fea, FD, 2, Wsr, sr_b, out + (size_t)Bq * LOC * 2048, 300, 0,
        Bq * NSS, 300, FD);
}